// round 17
// baseline (speedup 1.0000x reference)
#include <cuda_runtime.h>
#include <cuda_bf16.h>

#define GS 32
#define NN 16
#define SLICES 8
#define ATOM_TYPE 6

// Single MUFU EX2 regardless of compile flags.
__device__ __forceinline__ float ex2(float x) {
    float r;
    asm("ex2.approx.ftz.f32 %0, %1;" : "=f"(r) : "f"(x));
    return r;
}

// Streaming 128-bit store (evict-first: output is write-once).
__device__ __forceinline__ void stg_cs(float* p, float4 v) {
    asm volatile("st.global.cs.v4.f32 [%0], {%1,%2,%3,%4};"
                 :: "l"(p), "f"(v.x), "f"(v.y), "f"(v.z), "f"(v.w));
}

// out[b,a,i,j,k] = sum_{n: an[a,n]==6} exp(c*||grid - dv||^2), c = -0.5/sigma^2.
// Champion math (R14): separable Gaussian ratio recurrence, 3 ex2 seeds +
// ratio walks per neighbor; dv rows in the register file, shfl-broadcast into
// a memory-free mask loop; one parallel memory round trip at block start;
// register-only, barrier-free.
// R17 shape: 256 blocks x 512 threads (half the front chains / CTA deliveries
// of the 512x256 champion; per-thread work identical). t>>8 picks the 8-slice
// i-group, t&255 gives (j, k0). 2 CTAs/SM at 54 regs -> single wave.
__global__ __launch_bounds__(512) void voxel_kernel(
    const float* __restrict__ dv,     // (B, A, N, 3)
    const int*   __restrict__ an,     // (A, N) int32
    const float* __restrict__ sigma,  // (1,)
    float* __restrict__ out)          // (B, A, G, G, G)
{
    const int ba = blockIdx.x;        // b*32 + a
    const int a  = ba & 31;
    const int ih = blockIdx.y;        // i half: slices [ih*16, ih*16+16)
    const int t  = threadIdx.x;       // 0..511
    const int tt = t & 255;
    const int sg8 = t >> 8;           // which 8-slice group within the half
    const int i0 = ih * 16 + sg8 * 8; // first i-slice for this thread
    const int j  = tt >> 3;
    const int k0 = (tt & 7) << 2;
    const int lane = t & 31;

    // One parallel round trip: sigma, an, and dv all issued together.
    const float sg = __ldg(sigma);
    bool act = false;
    float dxl = 0.f, dyl = 0.f, dzl = 0.f;
    if (lane < NN) {
        const float* p = dv + (ba * NN + lane) * 3;
        dxl = p[0];
        dyl = p[1];
        dzl = p[2];
        act = (an[a * NN + lane] == ATOM_TYPE);
    }
    unsigned mask = __ballot_sync(0xffffffffu, act);

    const float step = 8.0f / 31.0f;
    const float c2 = (-0.5f / (sg * sg)) * 1.4426950408889634f;  // coeff * log2(e)
    const float q  = ex2(2.0f * c2 * step * step);               // hoisted constant

    const float ti0 = -4.0f + (float)i0 * step;
    const float tj  = -4.0f + (float)j * step;
    const float tk0 = -4.0f + (float)k0 * step;

    float4 acc[SLICES];
    #pragma unroll
    for (int ii = 0; ii < SLICES; ++ii) acc[ii] = make_float4(0.f, 0.f, 0.f, 0.f);

    while (mask) {
        const int n = __ffs(mask) - 1;
        mask &= mask - 1;

        // Neighbor displacement via register-file broadcast (no memory).
        const float dx = __shfl_sync(0xffffffffu, dxl, n);
        const float dy = __shfl_sync(0xffffffffu, dyl, n);
        const float dz = __shfl_sync(0xffffffffu, dzl, n);

        const float ddx = ti0 - dx;
        const float ddy = tj  - dy;
        const float ddz = tk0 - dz;

        // Seeds: base value at (i0, j, k0) and first-step ratios along z and x.
        const float argb = c2 * (ddx * ddx + ddy * ddy + ddz * ddz);
        const float e0 = ex2(argb);
        float rz = ex2(c2 * fmaf(2.0f * ddz, step, step * step));
        float rx = ex2(c2 * fmaf(2.0f * ddx, step, step * step));

        // z-row at slice i0 via ratio walk (4 values).
        const float v0 = e0;
        const float v1 = v0 * rz;  rz *= q;
        const float v2 = v1 * rz;  rz *= q;
        const float v3 = v2 * rz;

        // x multipliers X1..X7 via ratio walk; X0 = 1.
        float xm[SLICES];
        xm[0] = 1.0f;
        xm[1] = rx;
        #pragma unroll
        for (int ii = 2; ii < SLICES; ++ii) {
            rx *= q;
            xm[ii] = xm[ii - 1] * rx;
        }

        acc[0].x += v0;  acc[0].y += v1;  acc[0].z += v2;  acc[0].w += v3;
        #pragma unroll
        for (int ii = 1; ii < SLICES; ++ii) {
            acc[ii].x = fmaf(xm[ii], v0, acc[ii].x);
            acc[ii].y = fmaf(xm[ii], v1, acc[ii].y);
            acc[ii].z = fmaf(xm[ii], v2, acc[ii].z);
            acc[ii].w = fmaf(xm[ii], v3, acc[ii].w);
        }
    }

    float* outp = out + ba * (GS * GS * GS)
                      + i0 * (GS * GS)
                      + 4 * tt;   // j*32 + k0 == 4*tt
    #pragma unroll
    for (int ii = 0; ii < SLICES; ++ii)
        stg_cs(outp + ii * (GS * GS), acc[ii]);
}

extern "C" void kernel_launch(void* const* d_in, const int* in_sizes, int n_in,
                              void* d_out, int out_size) {
    const float* dv    = (const float*)d_in[0];   // distance_vector (B,32,16,3)
    const int*   an    = (const int*)d_in[1];     // atomic_numbers (32,16) int32
    const float* sigma = (const float*)d_in[2];   // (1,)
    float* out = (float*)d_out;

    const int B = in_sizes[0] / (32 * 16 * 3);    // derive batch from input size
    dim3 grid(B * 32, 2);                         // (128, 2) = 256 blocks
    voxel_kernel<<<grid, 512>>>(dv, an, sigma, out);
}